// round 15
// baseline (speedup 1.0000x reference)
#include <cuda_runtime.h>
#include <cuda_fp16.h>
#include <string.h>

// LearnableConvCensus: depthwise 3x3 conv (multiplier 8) -> sigmoid -> mean over 8.
// B=4, C=64, H=W=256, pad=1.
//
// sigmoid(z) = 0.5 + 0.5*tanh(z/2); fold 0.5*temperature[c] into pre-scaled
// weights/bias. out = 0.5 + (sum_m tanh_m) / 16.
//
// R15: TENSOR CORES. Per 16-pixel tile, ONE mma.m16n8k16 (fp16 in, fp32 acc)
// computes all 9 taps x 8 multipliers: A[pixel][k] = shifted input window
// (K slots: [h0w0,h0w1,h0w2,Z, h1w0,h1w1,h1w2,Z, h2w0,h2w1,h2w2,Z, Z,Z,Z,Z]),
// B[k][m] = per-channel weights (per-thread constant fragment), C = bias.
// A-fragments built from an fp16 smem tile via LDS.32 pairs + PRMT (handles
// the 2-byte window shift). Epilogue: tanh.approx.f16x2 + shfl-xor reduction
// over the 8 multipliers. SIMT-FMA paradigm plateaued at ~57us over 8 variants.

#define B_ 4
#define C_ 64
#define H_ 256
#define W_ 256
#define R_ 32                 // output rows per block
#define NROWS 34              // input rows incl. halo
#define SROWH 272             // tile row stride in fp16 (4 left pad + 256 + right)

typedef unsigned int u32;
typedef unsigned long long ull;

__device__ __forceinline__ u32 f2h2(float hi, float lo) {
    u32 h;
    asm("cvt.rn.f16x2.f32 %0, %1, %2;" : "=r"(h) : "f"(hi), "f"(lo));
    return h;
}
__device__ __forceinline__ u32 tanh2(u32 h) {
    u32 t;
    asm("tanh.approx.f16x2 %0, %1;" : "=r"(t) : "r"(h));
    return t;
}
__device__ __forceinline__ u32 hadd2(u32 a, u32 b) {
    u32 d;
    asm("add.rn.f16x2 %0, %1, %2;" : "=r"(d) : "r"(a), "r"(b));
    return d;
}
__device__ __forceinline__ u32 prmt(u32 a, u32 b, u32 s) {
    u32 d;
    asm("prmt.b32 %0, %1, %2, %3;" : "=r"(d) : "r"(a), "r"(b), "r"(s));
    return d;
}

__global__ __launch_bounds__(128, 8)
void census_kernel(const float* __restrict__ x, const float* __restrict__ w,
                   const float* __restrict__ bias, const float* __restrict__ temp,
                   float* __restrict__ out) {
    __shared__ __align__(16) __half smh[NROWS * SROWH];   // fp16 input tile

    const int bid   = blockIdx.x;
    const int strip = bid & 7;          // H_/R_ = 8 strips
    const int c     = (bid >> 3) & 63;
    const int b     = bid >> 9;
    const int h0    = strip * R_;
    const int tid   = threadIdx.x;
    const int warp  = tid >> 5;
    const int lane  = tid & 31;
    const int q     = lane & 3;         // thread-in-group (k-pair / multiplier-pair)
    const int g     = lane >> 2;        // group id (pixel / multiplier index)

    const float* xp = x + ((size_t)(b * C_ + c) * H_) * W_;

    // ---- fp16 tile: smh[r][col+4] = x[h0+r-1][col]; idx 3 (col -1) and
    // idx 260 (col 256) are the zero conv padding. idx 0..3, 260..263 zeroed.
    #pragma unroll
    for (int i = tid; i < NROWS * 64; i += 128) {
        const int r  = i >> 6;
        const int c4 = (i & 63) << 2;
        const int gh = h0 + r - 1;
        float4 v = make_float4(0.f, 0.f, 0.f, 0.f);
        if (gh >= 0 && gh < H_) v = *(const float4*)(xp + gh * W_ + c4);
        const u32 h01 = f2h2(v.y, v.x);
        const u32 h23 = f2h2(v.w, v.z);
        *(ull*)(smh + r * SROWH + 4 + c4) = ((ull)h23 << 32) | h01;  // 8B aligned
    }
    if (tid < NROWS) {
        *(ull*)(smh + tid * SROWH)       = 0ull;   // idx 0..3
        *(ull*)(smh + tid * SROWH + 260) = 0ull;   // idx 260..263
    }

    // ---- B fragment (weights) + C fragment (bias), per-thread constants.
    // w layout HWIO flattened: T[j] = w[j*512 + c*8 + m], j = kh*3+kw, m = g.
    // K-slot layout: b0 = (B[2q], B[2q+1]), b1 = (B[2q+8], B[2q+9]).
    const float sc = 0.5f * __ldg(&temp[c]);
    float T[9];
    #pragma unroll
    for (int j = 0; j < 9; j++) T[j] = __ldg(&w[j * 512 + (c << 3) + g]) * sc;
    u32 bf0, bf1;
    if (q == 0)      { bf0 = f2h2(T[1], T[0]); bf1 = f2h2(T[7], T[6]); }
    else if (q == 1) { bf0 = f2h2(0.f,  T[2]); bf1 = f2h2(0.f,  T[8]); }
    else if (q == 2) { bf0 = f2h2(T[4], T[3]); bf1 = 0u; }
    else             { bf0 = f2h2(0.f,  T[5]); bf1 = 0u; }
    const float cb0 = __ldg(&bias[(c << 3) + 2 * q])     * sc;  // D col 2q
    const float cb1 = __ldg(&bias[(c << 3) + 2 * q + 1]) * sc;  // D col 2q+1
    __syncthreads();

    // A-fragment addressing (thread-const parts):
    //   pixel p = col0 + g (+8 for a1/a3); fp16 idx = p + 3 + 2*(q&1)
    //   byte = 2*idx; 4B base + PRMT handles odd-idx pairs.
    //   rowA (k-lo) = tile row r + (q>>1); rowB (k-hi) = q<2 ? r+2 : r
    const int  tcA = (2 * (g + 3 + 2 * (q & 1))) & ~3;
    const u32  sel = (g & 1) ? 0x3210u : 0x5432u;   // idx even : odd
    const int  rAo = (q >> 1);
    const int  rBo = (q < 2) ? 2 : 0;

    float* outp = out + (((size_t)(b * C_ + c) * H_) + h0) * W_;

    // warp handles rows 8*warp .. 8*warp+7, 16 col-tiles each
    #pragma unroll 1
    for (int rr = 0; rr < 8; rr++) {
        const int r = (warp << 3) + rr;
        const char* rowA = (const char*)(smh + (r + rAo) * SROWH);
        const char* rowB = (const char*)(smh + (r + rBo) * SROWH);
        float* orow = outp + r * W_;

        #pragma unroll 2
        for (int t = 0; t < 16; t++) {
            const int col0 = t << 4;
            const char* pa = rowA + (col0 << 1) + tcA;
            const char* pb = rowB + (col0 << 1) + tcA;
            const u32 a0 = prmt(*(const u32*)(pa),      *(const u32*)(pa + 4),  sel);
            const u32 a1 = prmt(*(const u32*)(pa + 16), *(const u32*)(pa + 20), sel);
            const u32 a2 = prmt(*(const u32*)(pb),      *(const u32*)(pb + 4),  sel);
            const u32 a3 = prmt(*(const u32*)(pb + 16), *(const u32*)(pb + 20), sel);

            float d0, d1, d2, d3;
            asm("mma.sync.aligned.m16n8k16.row.col.f32.f16.f16.f32 "
                "{%0,%1,%2,%3}, {%4,%5,%6,%7}, {%8,%9}, {%10,%11,%12,%13};"
                : "=f"(d0), "=f"(d1), "=f"(d2), "=f"(d3)
                : "r"(a0), "r"(a1), "r"(a2), "r"(a3),
                  "r"(bf0), "r"(bf1),
                  "f"(cb0), "f"(cb1), "f"(cb0), "f"(cb1));

            // pixel g: (m=2q, m=2q+1) in d0,d1; pixel g+8 in d2,d3
            u32 t0 = tanh2(f2h2(d1, d0));
            u32 t1 = tanh2(f2h2(d3, d2));
            t0 = hadd2(t0, __shfl_xor_sync(0xFFFFFFFFu, t0, 1));
            t0 = hadd2(t0, __shfl_xor_sync(0xFFFFFFFFu, t0, 2));
            t1 = hadd2(t1, __shfl_xor_sync(0xFFFFFFFFu, t1, 1));
            t1 = hadd2(t1, __shfl_xor_sync(0xFFFFFFFFu, t1, 2));
            if (q == 0) {
                __half2 h0v, h1v;
                memcpy(&h0v, &t0, 4);
                memcpy(&h1v, &t1, 4);
                const float2 f0 = __half22float2(h0v);
                const float2 f1 = __half22float2(h1v);
                orow[col0 + g]     = fmaf(f0.x + f0.y, 0.0625f, 0.5f);
                orow[col0 + g + 8] = fmaf(f1.x + f1.y, 0.0625f, 0.5f);
            }
        }
    }
}

extern "C" void kernel_launch(void* const* d_in, const int* in_sizes, int n_in,
                              void* d_out, int out_size) {
    const float* x    = (const float*)d_in[0];
    const float* w    = (const float*)d_in[1];
    const float* bias = (const float*)d_in[2];
    const float* temp = (const float*)d_in[3];
    float* out = (float*)d_out;

    const int grid = B_ * C_ * (H_ / R_);   // 4*64*8 = 2048 blocks
    census_kernel<<<grid, 128>>>(x, w, bias, temp, out);
}

// round 16
// speedup vs baseline: 1.1313x; 1.1313x over previous
#include <cuda_runtime.h>
#include <cuda_fp16.h>
#include <string.h>

// LearnableConvCensus: depthwise 3x3 conv (multiplier 8) -> sigmoid -> mean over 8.
// B=4, C=64, H=W=256, pad=1.
//
// sigmoid(z) = 0.5 + 0.5*tanh(z/2); fold 0.5*temperature[c] into pre-scaled
// weights/bias. out = 0.5 + (sum_m tanh_m) / 16.
//
// R16: tensor-core path (validated correct in R15) minus its two overheads:
//  (a) m-reduction via a SECOND mma (D1 layout == A2 layout; B2 = 1/16,
//      C2 = 0.5) instead of 4 shfl + hadds per tile;
//  (b) predicated A-gather: q-odd lanes skip the 2nd klo word (feeds a zero
//      B column), q>=2 lanes skip ALL k-hi words (B rows 12-15 are zero) —
//      inactive-lane LDS generate no L1 wavefronts (L1 was 69.8% = binding).

#define B_ 4
#define C_ 64
#define H_ 256
#define W_ 256
#define R_ 32                 // output rows per block
#define NROWS 34              // input rows incl. halo
#define SROWH 272             // tile row stride in fp16 (4 left pad + 256 + pad)

typedef unsigned int u32;
typedef unsigned long long ull;

__device__ __forceinline__ u32 f2h2(float hi, float lo) {
    u32 h;
    asm("cvt.rn.f16x2.f32 %0, %1, %2;" : "=r"(h) : "f"(hi), "f"(lo));
    return h;
}
__device__ __forceinline__ u32 tanh2(u32 h) {
    u32 t;
    asm("tanh.approx.f16x2 %0, %1;" : "=r"(t) : "r"(h));
    return t;
}
__device__ __forceinline__ u32 prmt(u32 a, u32 b, u32 s) {
    u32 d;
    asm("prmt.b32 %0, %1, %2, %3;" : "=r"(d) : "r"(a), "r"(b), "r"(s));
    return d;
}

__global__ __launch_bounds__(128, 8)
void census_kernel(const float* __restrict__ x, const float* __restrict__ w,
                   const float* __restrict__ bias, const float* __restrict__ temp,
                   float* __restrict__ out) {
    __shared__ __align__(16) __half smh[NROWS * SROWH];   // fp16 input tile

    const int bid   = blockIdx.x;
    const int strip = bid & 7;          // H_/R_ = 8 strips
    const int c     = (bid >> 3) & 63;
    const int b     = bid >> 9;
    const int h0    = strip * R_;
    const int tid   = threadIdx.x;
    const int warp  = tid >> 5;
    const int lane  = tid & 31;
    const int q     = lane & 3;         // k-pair / D-column-pair index
    const int g     = lane >> 2;        // pixel / multiplier index

    const float* xp = x + ((size_t)(b * C_ + c) * H_) * W_;

    // ---- fp16 tile: smh[r][col+4] = x[h0+r-1][col]; idx 3 (col -1) and
    // idx 260 (col 256) are the zero conv padding. idx 0..3, 260..263 zeroed.
    #pragma unroll
    for (int i = tid; i < NROWS * 64; i += 128) {
        const int r  = i >> 6;
        const int c4 = (i & 63) << 2;
        const int gh = h0 + r - 1;
        float4 v = make_float4(0.f, 0.f, 0.f, 0.f);
        if (gh >= 0 && gh < H_) v = *(const float4*)(xp + gh * W_ + c4);
        const u32 h01 = f2h2(v.y, v.x);
        const u32 h23 = f2h2(v.w, v.z);
        *(ull*)(smh + r * SROWH + 4 + c4) = ((ull)h23 << 32) | h01;
    }
    if (tid < NROWS) {
        *(ull*)(smh + tid * SROWH)       = 0ull;
        *(ull*)(smh + tid * SROWH + 260) = 0ull;
    }

    // ---- B fragment (weights) + C fragment (bias), per-thread constants.
    // w layout HWIO flattened: T[j] = w[j*512 + c*8 + m], j = kh*3+kw, m = g.
    // K slots: [h0w0,h0w1,h0w2,Z, h1w0,h1w1,h1w2,Z, h2w0,h2w1,h2w2,Z, Z,Z,Z,Z]
    const float sc = 0.5f * __ldg(&temp[c]);
    float T[9];
    #pragma unroll
    for (int j = 0; j < 9; j++) T[j] = __ldg(&w[j * 512 + (c << 3) + g]) * sc;
    u32 bf0, bf1;
    if (q == 0)      { bf0 = f2h2(T[1], T[0]); bf1 = f2h2(T[7], T[6]); }
    else if (q == 1) { bf0 = f2h2(0.f,  T[2]); bf1 = f2h2(0.f,  T[8]); }
    else if (q == 2) { bf0 = f2h2(T[4], T[3]); bf1 = 0u; }
    else             { bf0 = f2h2(0.f,  T[5]); bf1 = 0u; }
    const float cb0 = __ldg(&bias[(c << 3) + 2 * q])     * sc;  // D col 2q
    const float cb1 = __ldg(&bias[(c << 3) + 2 * q + 1]) * sc;  // D col 2q+1
    const u32 os2 = f2h2(0.0625f, 0.0625f);                     // mma2 B value
    __syncthreads();

    // A-gather constants:
    //   klo pair starts at fp16 idx col0+g+3+2(q&1); byte base 4B-rounded.
    //   sel: g odd (word-aligned): q even -> whole pair from L0 (0x3210),
    //        q odd -> single value + zero-hi from L1=0 (0x5410);
    //        g even (straddle): lo from L0 bytes 2,3 + hi from L1 (0x5432).
    //   nL1: 2nd klo word carries real data only for q even & g even;
    //        q odd's 2nd value feeds a ZERO B column (and L1=0 keeps it finite).
    //   k-hi rows (a2,a3) multiply B rows 8..15; those are zero for q>=2.
    const int  tcA  = (2 * (g + 3 + 2 * (q & 1))) & ~3;
    const u32  sel  = (g & 1) ? ((q & 1) ? 0x5410u : 0x3210u) : 0x5432u;
    const bool nL1  = !(q & 1) && !(g & 1);
    const bool nLo2 = (q < 2);
    const bool nL12 = nL1 && nLo2;
    const int  rAo  = q >> 1;           // klo row offset (0 or 1)

    float* outp = out + (((size_t)(b * C_ + c) * H_) + h0) * W_;

    // warp handles rows 8*warp .. 8*warp+7, 16 col-tiles each
    #pragma unroll 1
    for (int rr = 0; rr < 8; rr++) {
        const int r = (warp << 3) + rr;
        const char* rowA = (const char*)(smh + (r + rAo) * SROWH) + tcA;
        const char* rowB = (const char*)(smh + (r + 2)   * SROWH) + tcA;
        float* orow = outp + r * W_;

        #pragma unroll 4
        for (int t = 0; t < 16; t++) {
            const int col0 = t << 4;
            const char* pa = rowA + (col0 << 1);
            const char* pb = rowB + (col0 << 1);
            const u32 x0 = *(const u32*)pa;
            const u32 x1 = nL1  ? *(const u32*)(pa + 4)  : 0u;
            const u32 y0 = *(const u32*)(pa + 16);
            const u32 y1 = nL1  ? *(const u32*)(pa + 20) : 0u;
            const u32 z0 = nLo2 ? *(const u32*)(pb)      : 0u;
            const u32 z1 = nL12 ? *(const u32*)(pb + 4)  : 0u;
            const u32 u0 = nLo2 ? *(const u32*)(pb + 16) : 0u;
            const u32 u1 = nL12 ? *(const u32*)(pb + 20) : 0u;
            const u32 a0 = prmt(x0, x1, sel);
            const u32 a1 = prmt(y0, y1, sel);
            const u32 a2 = prmt(z0, z1, sel);
            const u32 a3 = prmt(u0, u1, sel);

            float d0, d1, d2, d3;
            asm("mma.sync.aligned.m16n8k16.row.col.f32.f16.f16.f32 "
                "{%0,%1,%2,%3}, {%4,%5,%6,%7}, {%8,%9}, {%10,%11,%12,%13};"
                : "=f"(d0), "=f"(d1), "=f"(d2), "=f"(d3)
                : "r"(a0), "r"(a1), "r"(a2), "r"(a3),
                  "r"(bf0), "r"(bf1),
                  "f"(cb0), "f"(cb1), "f"(cb0), "f"(cb1));

            // m-reduction mma: A2 = tanh matrix (pixel x m), layout == D1;
            // B2 = 1/16 (k<8), C2 = 0.5 -> D2[:,0] = final output pixels.
            const u32 t0 = tanh2(f2h2(d1, d0));
            const u32 t1 = tanh2(f2h2(d3, d2));
            float e0, e1, e2, e3;
            asm("mma.sync.aligned.m16n8k16.row.col.f32.f16.f16.f32 "
                "{%0,%1,%2,%3}, {%4,%5,%6,%7}, {%8,%9}, {%10,%11,%12,%13};"
                : "=f"(e0), "=f"(e1), "=f"(e2), "=f"(e3)
                : "r"(t0), "r"(t1), "r"(0u), "r"(0u),
                  "r"(os2), "r"(0u),
                  "f"(0.5f), "f"(0.5f), "f"(0.5f), "f"(0.5f));

            if (q == 0) {
                orow[col0 + g]     = e0;   // D2[g][0]
                orow[col0 + g + 8] = e2;   // D2[g+8][0]
            }
        }
    }
}

extern "C" void kernel_launch(void* const* d_in, const int* in_sizes, int n_in,
                              void* d_out, int out_size) {
    const float* x    = (const float*)d_in[0];
    const float* w    = (const float*)d_in[1];
    const float* bias = (const float*)d_in[2];
    const float* temp = (const float*)d_in[3];
    float* out = (float*)d_out;

    const int grid = B_ * C_ * (H_ / R_);   // 4*64*8 = 2048 blocks
    census_kernel<<<grid, 128>>>(x, w, bias, temp, out);
}